// round 2
// baseline (speedup 1.0000x reference)
#include <cuda_runtime.h>

// FBGCN layer, restructured:
//   Hh = d_inv @ (lap @ (d_inv @ relu(x @ W_high)))   [3x (4096x4096x256) GEMMs]
//   Hl = GCNConv(x, edge_index, W_conv, b_conv)
//   out = aL*Hl + aH*Hh
//
// Inputs (metadata order):
//  0: x        [4096,256]  f32
//  1: edge_index [2,131072] int64-declared (may actually be int32 — detected at runtime)
//  2: lap      [4096,4096] f32
//  3: d_inv    [4096,4096] f32
//  4: W_high   [256,256]   f32
//  5: W_conv   [256,256]   f32
//  6: b_conv   [256]       f32
//  7: aL       [1]         f32
//  8: aH       [1]         f32
// out: [4096,256] f32

static constexpr int N_NODES = 4096;
static constexpr int DIM     = 256;
static constexpr int N_EDGES = 131072;

__device__ float g_A[N_NODES * DIM];   // scratch: R / XW_conv
__device__ float g_B[N_NODES * DIM];   // scratch: T1 / Hh
__device__ float g_C[N_NODES * DIM];   // scratch: T2
__device__ float g_dis[N_NODES];       // deg -> deg_inv_sqrt
__device__ int   g_src[N_EDGES];
__device__ int   g_dst[N_EDGES];
__device__ int   g_is64;               // 1 if edge_index is int64, 0 if int32

// ---------------------------------------------------------------------------
// Edge-index dtype detection + normalization.
// Probes only the first 256 uint32 words (valid under both interpretations).
// int64 little-endian values in [0,4096): odd words are all zero.
// int32 data: odd words are random indices, ~never all zero.
// ---------------------------------------------------------------------------
__global__ void detect_dtype_kernel(const unsigned int* __restrict__ raw)
{
    if (threadIdx.x == 0 && blockIdx.x == 0) {
        int is64 = 1;
        #pragma unroll 1
        for (int i = 0; i < 128; i++) {
            if (raw[2 * i + 1] != 0u) { is64 = 0; break; }
        }
        g_is64 = is64;
    }
}

__global__ void convert_edges_kernel(const void* __restrict__ rawp)
{
    int e = blockIdx.x * blockDim.x + threadIdx.x;
    if (e >= N_EDGES) return;
    if (g_is64) {
        const long long* ei = (const long long*)rawp;
        g_src[e] = (int)ei[e];
        g_dst[e] = (int)ei[N_EDGES + e];
    } else {
        const int* ei = (const int*)rawp;
        g_src[e] = ei[e];
        g_dst[e] = ei[N_EDGES + e];
    }
}

// ---------------------------------------------------------------------------
// SGEMM: C[M,N] = A[M,K] @ B[K,N], row-major, fp32.
// BM=128, BN=64, BK=16, 256 threads, 8x4 per thread.
// Requires M%128==0, N%64==0, K%16==0 (true for all calls here).
// ---------------------------------------------------------------------------
template <bool RELU>
__global__ __launch_bounds__(256, 2) void sgemm_kernel(
    const float* __restrict__ A, const float* __restrict__ B,
    float* __restrict__ C, int M, int N, int K)
{
    __shared__ float As[16][132];   // k-major, padded (row stride 528B, 16B-aligned)
    __shared__ float Bs[16][64];

    const int t  = threadIdx.x;
    const int tx = t & 15;          // 16 threads along N (4 cols each)
    const int ty = t >> 4;          // 16 threads along M (8 rows each)
    const int m0 = blockIdx.y * 128;
    const int n0 = blockIdx.x * 64;

    const float* Ap = A + (size_t)m0 * K;
    const float* Bp = B + n0;

    float acc[8][4];
    #pragma unroll
    for (int i = 0; i < 8; i++)
        #pragma unroll
        for (int j = 0; j < 4; j++) acc[i][j] = 0.f;

    for (int k0 = 0; k0 < K; k0 += 16) {
        // A tile: 128x16 = 512 float4s, 2 per thread, stored k-major.
        #pragma unroll
        for (int i = 0; i < 2; i++) {
            int f   = t + i * 256;
            int row = f >> 2;               // 0..127
            int kc  = (f & 3) << 2;         // 0,4,8,12
            float4 v = *reinterpret_cast<const float4*>(Ap + (size_t)row * K + k0 + kc);
            As[kc + 0][row] = v.x;
            As[kc + 1][row] = v.y;
            As[kc + 2][row] = v.z;
            As[kc + 3][row] = v.w;
        }
        // B tile: 16x64 = 256 float4s, 1 per thread.
        {
            int kr = t >> 4;                // 0..15
            int c4 = (t & 15) << 2;         // 0..60
            float4 v = *reinterpret_cast<const float4*>(Bp + (size_t)(k0 + kr) * N + c4);
            *reinterpret_cast<float4*>(&Bs[kr][c4]) = v;
        }
        __syncthreads();

        #pragma unroll
        for (int k = 0; k < 16; k++) {
            float a[8], b[4];
            float4 a0 = *reinterpret_cast<const float4*>(&As[k][ty * 8]);
            float4 a1 = *reinterpret_cast<const float4*>(&As[k][ty * 8 + 4]);
            a[0]=a0.x; a[1]=a0.y; a[2]=a0.z; a[3]=a0.w;
            a[4]=a1.x; a[5]=a1.y; a[6]=a1.z; a[7]=a1.w;
            float4 b0 = *reinterpret_cast<const float4*>(&Bs[k][tx * 4]);
            b[0]=b0.x; b[1]=b0.y; b[2]=b0.z; b[3]=b0.w;
            #pragma unroll
            for (int i = 0; i < 8; i++)
                #pragma unroll
                for (int j = 0; j < 4; j++)
                    acc[i][j] = fmaf(a[i], b[j], acc[i][j]);
        }
        __syncthreads();
    }

    #pragma unroll
    for (int i = 0; i < 8; i++) {
        int r = m0 + ty * 8 + i;
        float4 v;
        v.x = acc[i][0]; v.y = acc[i][1]; v.z = acc[i][2]; v.w = acc[i][3];
        if (RELU) {
            v.x = fmaxf(v.x, 0.f); v.y = fmaxf(v.y, 0.f);
            v.z = fmaxf(v.z, 0.f); v.w = fmaxf(v.w, 0.f);
        }
        *reinterpret_cast<float4*>(C + (size_t)r * N + n0 + tx * 4) = v;
    }
}

// ---------------------------------------------------------------------------
// GCN branch helpers
// ---------------------------------------------------------------------------
__global__ void deg_init_kernel()
{
    int i = blockIdx.x * blockDim.x + threadIdx.x;
    if (i < N_NODES) g_dis[i] = 1.0f;   // self-loop contributes 1
}

__global__ void deg_count_kernel()
{
    int e = blockIdx.x * blockDim.x + threadIdx.x;
    if (e < N_EDGES) atomicAdd(&g_dis[g_dst[e]], 1.0f);
}

__global__ void deg_finalize_kernel()
{
    int i = blockIdx.x * blockDim.x + threadIdx.x;
    if (i < N_NODES) g_dis[i] = rsqrtf(g_dis[i]);   // deg >= 1 always
}

// out[i][c] = XW[i][c] * dis[i]^2   (self-loop term, initializes d_out)
__global__ void selfloop_init_kernel(float* __restrict__ out)
{
    int id = blockIdx.x * blockDim.x + threadIdx.x;   // over N*DIM/4
    if (id < N_NODES * DIM / 4) {
        int row = id / (DIM / 4);
        float s = g_dis[row];
        s = s * s;
        float4 v = reinterpret_cast<const float4*>(g_A)[id];
        v.x *= s; v.y *= s; v.z *= s; v.w *= s;
        reinterpret_cast<float4*>(out)[id] = v;
    }
}

// Edge scatter: out[dst] += XW[src] * dis[src]*dis[dst]
// One thread per (edge, 4-col group): E * 64 threads.
__global__ void scatter_kernel(float* __restrict__ out)
{
    int id = blockIdx.x * blockDim.x + threadIdx.x;
    if (id >= N_EDGES * (DIM / 4)) return;
    int e   = id >> 6;             // DIM/4 = 64 groups per edge
    int col = (id & 63) << 2;
    int src = g_src[e];
    int dst = g_dst[e];
    float norm = g_dis[src] * g_dis[dst];
    float4 v = *reinterpret_cast<const float4*>(g_A + (size_t)src * DIM + col);
    float* o = out + (size_t)dst * DIM + col;
    atomicAdd(o + 0, v.x * norm);
    atomicAdd(o + 1, v.y * norm);
    atomicAdd(o + 2, v.z * norm);
    atomicAdd(o + 3, v.w * norm);
}

// out = aL*(out + b) + aH*Hh
__global__ void combine_kernel(float* __restrict__ out,
                               const float* __restrict__ b,
                               const float* __restrict__ aLp,
                               const float* __restrict__ aHp)
{
    int id = blockIdx.x * blockDim.x + threadIdx.x;   // over N*DIM/4
    if (id >= N_NODES * DIM / 4) return;
    float aL = aLp[0], aH = aHp[0];
    int c4 = (id & (DIM / 4 - 1)) << 2;
    float4 hl = reinterpret_cast<const float4*>(out)[id];
    float4 hh = reinterpret_cast<const float4*>(g_B)[id];
    float4 bb = *reinterpret_cast<const float4*>(b + c4);
    float4 r;
    r.x = aL * (hl.x + bb.x) + aH * hh.x;
    r.y = aL * (hl.y + bb.y) + aH * hh.y;
    r.z = aL * (hl.z + bb.z) + aH * hh.z;
    r.w = aL * (hl.w + bb.w) + aH * hh.w;
    reinterpret_cast<float4*>(out)[id] = r;
}

// ---------------------------------------------------------------------------
extern "C" void kernel_launch(void* const* d_in, const int* in_sizes, int n_in,
                              void* d_out, int out_size)
{
    const float* x      = (const float*)d_in[0];
    const void*  ei_raw = d_in[1];
    const float* lap    = (const float*)d_in[2];
    const float* d_inv  = (const float*)d_in[3];
    const float* W_high = (const float*)d_in[4];
    const float* W_conv = (const float*)d_in[5];
    const float* b_conv = (const float*)d_in[6];
    const float* aL     = (const float*)d_in[7];
    const float* aH     = (const float*)d_in[8];
    float*       out    = (float*)d_out;

    float *pA, *pB, *pC;
    cudaGetSymbolAddress((void**)&pA, g_A);
    cudaGetSymbolAddress((void**)&pB, g_B);
    cudaGetSymbolAddress((void**)&pC, g_C);

    // Normalize edge indices (dtype-agnostic)
    detect_dtype_kernel <<<1, 32>>>((const unsigned int*)ei_raw);
    convert_edges_kernel<<<N_EDGES / 256, 256>>>(ei_raw);

    dim3 g(DIM / 64, N_NODES / 128);    // 4 x 32

    // High-pass chain: R = relu(x @ W_high); T1 = d_inv @ R;
    // T2 = lap @ T1; Hh = d_inv @ T2 (into g_B)
    sgemm_kernel<true ><<<g, 256>>>(x,     W_high, pA, N_NODES, DIM, DIM);
    sgemm_kernel<false><<<g, 256>>>(d_inv, pA,     pB, N_NODES, DIM, N_NODES);
    // g_A free now -> XW_conv = x @ W_conv
    sgemm_kernel<false><<<g, 256>>>(x,     W_conv, pA, N_NODES, DIM, DIM);
    sgemm_kernel<false><<<g, 256>>>(lap,   pB,     pC, N_NODES, DIM, N_NODES);
    sgemm_kernel<false><<<g, 256>>>(d_inv, pC,     pB, N_NODES, DIM, N_NODES);

    // Degrees -> deg_inv_sqrt
    deg_init_kernel    <<<N_NODES / 256, 256>>>();
    deg_count_kernel   <<<N_EDGES / 256, 256>>>();
    deg_finalize_kernel<<<N_NODES / 256, 256>>>();

    // GCN aggregate into d_out
    int nvec = N_NODES * DIM / 4;
    selfloop_init_kernel<<<(nvec + 255) / 256, 256>>>(out);
    int nscat = N_EDGES * (DIM / 4);
    scatter_kernel<<<(nscat + 255) / 256, 256>>>(out);

    // out = aL*(Hl + b) + aH*Hh
    combine_kernel<<<(nvec + 255) / 256, 256>>>(out, b_conv, aL, aH);
}

// round 4
// speedup vs baseline: 1.7107x; 1.7107x over previous
#include <cuda_runtime.h>
#include <cuda_bf16.h>
#include <cstdint>

// FBGCN layer:
//   Hh = d_inv @ (lap @ (d_inv @ relu(x @ W_high)))  -- 3 mma.sync bf16-split GEMMs
//   Hl = GCNConv(x, edge_index, W_conv, b_conv)
//   out = aL*Hl + aH*Hh

static constexpr int N_NODES = 4096;
static constexpr int DIM     = 256;
static constexpr int N_EDGES = 131072;

// fp32 scratch
__device__ __align__(16) float g_A[N_NODES * DIM];   // R / XW_conv
__device__ __align__(16) float g_B[N_NODES * DIM];   // Hh
__device__ __align__(16) float g_C[N_NODES * DIM];   // T1 / T2
__device__ float g_dis[N_NODES];
__device__ int   g_src[N_EDGES];
__device__ int   g_dst[N_EDGES];
__device__ int   g_is64;

// bf16 split buffers
__device__ __align__(128) __nv_bfloat16 g_dinv_hi[N_NODES * N_NODES];
__device__ __align__(128) __nv_bfloat16 g_dinv_lo[N_NODES * N_NODES];
__device__ __align__(128) __nv_bfloat16 g_lap_hi [N_NODES * N_NODES];
__device__ __align__(128) __nv_bfloat16 g_lap_lo [N_NODES * N_NODES];
__device__ __align__(128) __nv_bfloat16 g_Bhi[DIM * N_NODES];   // [256 x 4096] transposed
__device__ __align__(128) __nv_bfloat16 g_Blo[DIM * N_NODES];

// ---------------------------------------------------------------------------
// PTX helpers (baseline ISA only: cp.async, ldmatrix, mma.sync)
// ---------------------------------------------------------------------------
__device__ __forceinline__ uint32_t smem_u32(const void* p) {
    uint32_t a;
    asm("{ .reg .u64 t; cvta.to.shared.u64 t, %1; cvt.u32.u64 %0, t; }" : "=r"(a) : "l"(p));
    return a;
}
__device__ __forceinline__ void cp_async16(uint32_t dst, const void* src) {
    asm volatile("cp.async.cg.shared.global [%0], [%1], 16;" :: "r"(dst), "l"(src) : "memory");
}
__device__ __forceinline__ void cp_commit() { asm volatile("cp.async.commit_group;" ::: "memory"); }
template <int N>
__device__ __forceinline__ void cp_wait() { asm volatile("cp.async.wait_group %0;" :: "n"(N) : "memory"); }

__device__ __forceinline__ void ldsm_x4(uint32_t* r, uint32_t addr) {
    asm volatile("ldmatrix.sync.aligned.m8n8.x4.shared.b16 {%0,%1,%2,%3}, [%4];"
        : "=r"(r[0]), "=r"(r[1]), "=r"(r[2]), "=r"(r[3]) : "r"(addr));
}
__device__ __forceinline__ void mma16816(float* c, const uint32_t* a, const uint32_t* b) {
    asm volatile("mma.sync.aligned.m16n8k16.row.col.f32.bf16.bf16.f32 "
        "{%0,%1,%2,%3}, {%4,%5,%6,%7}, {%8,%9}, {%0,%1,%2,%3};"
        : "+f"(c[0]), "+f"(c[1]), "+f"(c[2]), "+f"(c[3])
        : "r"(a[0]), "r"(a[1]), "r"(a[2]), "r"(a[3]), "r"(b[0]), "r"(b[1]));
}

// ---------------------------------------------------------------------------
// Edge-index dtype detect + normalize
// ---------------------------------------------------------------------------
__global__ void detect_dtype_kernel(const unsigned int* __restrict__ raw)
{
    if (threadIdx.x == 0 && blockIdx.x == 0) {
        int is64 = 1;
        #pragma unroll 1
        for (int i = 0; i < 128; i++)
            if (raw[2 * i + 1] != 0u) { is64 = 0; break; }
        g_is64 = is64;
    }
}
__global__ void convert_edges_kernel(const void* __restrict__ rawp)
{
    int e = blockIdx.x * blockDim.x + threadIdx.x;
    if (e >= N_EDGES) return;
    if (g_is64) {
        const long long* ei = (const long long*)rawp;
        g_src[e] = (int)ei[e];
        g_dst[e] = (int)ei[N_EDGES + e];
    } else {
        const int* ei = (const int*)rawp;
        g_src[e] = ei[e];
        g_dst[e] = ei[N_EDGES + e];
    }
}

// ---------------------------------------------------------------------------
// fp32 -> (hi, lo) bf16 split, same layout
// ---------------------------------------------------------------------------
__global__ void split_kernel(const float4* __restrict__ src,
                             uint2* __restrict__ hi, uint2* __restrict__ lo, int n4)
{
    int id = blockIdx.x * blockDim.x + threadIdx.x;
    if (id >= n4) return;
    float4 v = src[id];
    __nv_bfloat16 hx = __float2bfloat16(v.x), hy = __float2bfloat16(v.y);
    __nv_bfloat16 hz = __float2bfloat16(v.z), hw = __float2bfloat16(v.w);
    __nv_bfloat16 lx = __float2bfloat16(v.x - __bfloat162float(hx));
    __nv_bfloat16 ly = __float2bfloat16(v.y - __bfloat162float(hy));
    __nv_bfloat16 lz = __float2bfloat16(v.z - __bfloat162float(hz));
    __nv_bfloat16 lw = __float2bfloat16(v.w - __bfloat162float(hw));
    __nv_bfloat162 h01(hx, hy), h23(hz, hw), l01(lx, ly), l23(lz, lw);
    uint2 H, L;
    H.x = *(uint32_t*)&h01; H.y = *(uint32_t*)&h23;
    L.x = *(uint32_t*)&l01; L.y = *(uint32_t*)&l23;
    hi[id] = H; lo[id] = L;
}

// ---------------------------------------------------------------------------
// fp32 [4096 x 256] -> transposed bf16 splits [256 x 4096]
// ---------------------------------------------------------------------------
__global__ void transpose_split_kernel(const float* __restrict__ src,
                                       __nv_bfloat16* __restrict__ hi,
                                       __nv_bfloat16* __restrict__ lo)
{
    __shared__ float tile[32][33];
    int k0 = blockIdx.x * 32;
    int n0 = blockIdx.y * 32;
    int tx = threadIdx.x, ty = threadIdx.y;    // 32 x 8
    #pragma unroll
    for (int j = 0; j < 4; j++)
        tile[ty + j * 8][tx] = src[(size_t)(k0 + ty + j * 8) * DIM + n0 + tx];
    __syncthreads();
    #pragma unroll
    for (int j = 0; j < 4; j++) {
        int n = ty + j * 8;
        float v = tile[tx][n];
        __nv_bfloat16 h = __float2bfloat16(v);
        __nv_bfloat16 l = __float2bfloat16(v - __bfloat162float(h));
        size_t o = (size_t)(n0 + n) * N_NODES + k0 + tx;
        hi[o] = h; lo[o] = l;
    }
}

// ---------------------------------------------------------------------------
// mma.sync GEMM: C[4096x256] f32 = sum over 3 segments of Aseg @ Bseg^T
//   A segs [4096 x 4096] bf16 K-major rows; B segs [256 x 4096] bf16 K-major rows.
// CTA tile 128(M) x 64(N), BK=32, 256 threads / 8 warps (4x2), warp tile 32x32.
// 3-stage cp.async pipeline. Smem rows padded to 80B (conflict-free ldmatrix).
// ---------------------------------------------------------------------------
static constexpr int STAGES   = 3;
static constexpr int BK       = 32;
static constexpr int NIT      = 3 * N_NODES / BK;     // 384
static constexpr int ROWB     = 80;                   // bytes per padded smem row
static constexpr int A_BYTES  = 128 * ROWB;           // 10240
static constexpr int B_BYTES  = 64 * ROWB;            // 5120
static constexpr int STAGE_B  = A_BYTES + B_BYTES;    // 15360
static constexpr int GEMM_SMEM = STAGES * STAGE_B;    // 46080

__global__ __launch_bounds__(256, 1) void gemm_mma_kernel(
    const __nv_bfloat16* __restrict__ Ahi, const __nv_bfloat16* __restrict__ Alo,
    const __nv_bfloat16* __restrict__ Bhi, const __nv_bfloat16* __restrict__ Blo,
    float* __restrict__ C)
{
    extern __shared__ char smem[];
    const uint32_t sbase = smem_u32(smem);
    const int t    = threadIdx.x;
    const int lane = t & 31;
    const int wid  = t >> 5;
    const int wm   = wid >> 1;       // 0..3 -> M offset wm*32
    const int wn   = wid & 1;        // 0..1 -> N offset wn*32
    const int m0   = blockIdx.y * 128;
    const int n0   = blockIdx.x * 64;

    // segment base pointers (3-term split)
    const __nv_bfloat16* Aseg[3] = { Ahi, Ahi, Alo };
    const __nv_bfloat16* Bseg[3] = { Bhi, Blo, Bhi };

    // per-thread cp.async offsets
    const int arow = t >> 2;              // 0..63 (plus +64 for second task)
    const int ach  = t & 3;
    const size_t aOffG = (size_t)(m0 + arow) * N_NODES + ach * 8;
    const uint32_t aOffS = arow * ROWB + ach * 16;
    const size_t bOffG = (size_t)(n0 + arow) * N_NODES + ach * 8;
    const uint32_t bOffS = arow * ROWB + ach * 16;

    // ldmatrix lane addresses (byte offsets within stage)
    const uint32_t aLd = (uint32_t)(wm * 32 + (lane & 15)) * ROWB + (lane >> 4) * 16;
    const uint32_t bLd = A_BYTES +
        (uint32_t)(wn * 32 + ((lane >> 4) & 1) * 8 + (lane & 7)) * ROWB + ((lane >> 3) & 1) * 16;

    float acc[2][4][4];
    #pragma unroll
    for (int i = 0; i < 2; i++)
        #pragma unroll
        for (int j = 0; j < 4; j++)
            #pragma unroll
            for (int e = 0; e < 4; e++) acc[i][j][e] = 0.f;

    auto load_stage = [&](int c, int s) {
        if (c < NIT) {
            int seg = c >> 7;
            int k0  = (c & 127) << 5;
            const __nv_bfloat16* ap = Aseg[seg] + aOffG + k0;
            const __nv_bfloat16* bp = Bseg[seg] + bOffG + k0;
            uint32_t sb = sbase + s * STAGE_B;
            cp_async16(sb + aOffS, ap);
            cp_async16(sb + aOffS + 64 * ROWB, ap + (size_t)64 * N_NODES);
            cp_async16(sb + A_BYTES + bOffS, bp);
        }
        cp_commit();
    };

    #pragma unroll
    for (int p = 0; p < STAGES - 1; p++) load_stage(p, p);

    for (int c = 0; c < NIT; c++) {
        cp_wait<STAGES - 2>();
        __syncthreads();
        load_stage(c + STAGES - 1, (c + STAGES - 1) % STAGES);

        uint32_t sb = sbase + (c % STAGES) * STAGE_B;
        #pragma unroll
        for (int ks = 0; ks < 2; ks++) {
            uint32_t a[2][4], b[2][4];
            ldsm_x4(a[0], sb + aLd + ks * 32);
            ldsm_x4(a[1], sb + aLd + 16 * ROWB + ks * 32);
            ldsm_x4(b[0], sb + bLd + ks * 32);             // n-frags 0,1
            ldsm_x4(b[1], sb + bLd + 16 * ROWB + ks * 32); // n-frags 2,3
            #pragma unroll
            for (int i = 0; i < 2; i++) {
                mma16816(acc[i][0], a[i], &b[0][0]);
                mma16816(acc[i][1], a[i], &b[0][2]);
                mma16816(acc[i][2], a[i], &b[1][0]);
                mma16816(acc[i][3], a[i], &b[1][2]);
            }
        }
    }

    // epilogue: fragment -> global fp32
    const int gid = lane >> 2;     // 0..7
    const int tig = lane & 3;      // 0..3
    #pragma unroll
    for (int i = 0; i < 2; i++) {
        int rbase = m0 + wm * 32 + i * 16 + gid;
        #pragma unroll
        for (int j = 0; j < 4; j++) {
            int col = n0 + wn * 32 + j * 8 + tig * 2;
            float2 v0 = { acc[i][j][0], acc[i][j][1] };
            float2 v1 = { acc[i][j][2], acc[i][j][3] };
            *reinterpret_cast<float2*>(C + (size_t)rbase * DIM + col) = v0;
            *reinterpret_cast<float2*>(C + (size_t)(rbase + 8) * DIM + col) = v1;
        }
    }
}

// ---------------------------------------------------------------------------
// SIMT SGEMM for the two small x@W GEMMs (M=4096, N=256, K=256)
// ---------------------------------------------------------------------------
template <bool RELU>
__global__ __launch_bounds__(256, 2) void sgemm_kernel(
    const float* __restrict__ A, const float* __restrict__ B,
    float* __restrict__ C, int M, int N, int K)
{
    __shared__ float As[16][132];
    __shared__ float Bs[16][64];

    const int t  = threadIdx.x;
    const int tx = t & 15;
    const int ty = t >> 4;
    const int m0 = blockIdx.y * 128;
    const int n0 = blockIdx.x * 64;

    const float* Ap = A + (size_t)m0 * K;
    const float* Bp = B + n0;

    float acc[8][4];
    #pragma unroll
    for (int i = 0; i < 8; i++)
        #pragma unroll
        for (int j = 0; j < 4; j++) acc[i][j] = 0.f;

    for (int k0 = 0; k0 < K; k0 += 16) {
        #pragma unroll
        for (int i = 0; i < 2; i++) {
            int f = t + i * 256;
            int row = f >> 2;
            int kc  = (f & 3) << 2;
            float4 v = *reinterpret_cast<const float4*>(Ap + (size_t)row * K + k0 + kc);
            As[kc + 0][row] = v.x; As[kc + 1][row] = v.y;
            As[kc + 2][row] = v.z; As[kc + 3][row] = v.w;
        }
        {
            int kr = t >> 4;
            int c4 = (t & 15) << 2;
            float4 v = *reinterpret_cast<const float4*>(Bp + (size_t)(k0 + kr) * N + c4);
            *reinterpret_cast<float4*>(&Bs[kr][c4]) = v;
        }
        __syncthreads();
        #pragma unroll
        for (int k = 0; k < 16; k++) {
            float a[8], b[4];
            float4 a0 = *reinterpret_cast<const float4*>(&As[k][ty * 8]);
            float4 a1 = *reinterpret_cast<const float4*>(&As[k][ty * 8 + 4]);
            a[0]=a0.x; a[1]=a0.y; a[2]=a0.z; a[3]=a0.w;
            a[4]=a1.x; a[5]=a1.y; a[6]=a1.z; a[7]=a1.w;
            float4 b0 = *reinterpret_cast<const float4*>(&Bs[k][tx * 4]);
            b[0]=b0.x; b[1]=b0.y; b[2]=b0.z; b[3]=b0.w;
            #pragma unroll
            for (int i = 0; i < 8; i++)
                #pragma unroll
                for (int j = 0; j < 4; j++)
                    acc[i][j] = fmaf(a[i], b[j], acc[i][j]);
        }
        __syncthreads();
    }
    #pragma unroll
    for (int i = 0; i < 8; i++) {
        int r = m0 + ty * 8 + i;
        float4 v;
        v.x = acc[i][0]; v.y = acc[i][1]; v.z = acc[i][2]; v.w = acc[i][3];
        if (RELU) {
            v.x = fmaxf(v.x, 0.f); v.y = fmaxf(v.y, 0.f);
            v.z = fmaxf(v.z, 0.f); v.w = fmaxf(v.w, 0.f);
        }
        *reinterpret_cast<float4*>(C + (size_t)r * N + n0 + tx * 4) = v;
    }
}

// ---------------------------------------------------------------------------
// GCN branch
// ---------------------------------------------------------------------------
__global__ void deg_init_kernel()
{
    int i = blockIdx.x * blockDim.x + threadIdx.x;
    if (i < N_NODES) g_dis[i] = 1.0f;
}
__global__ void deg_count_kernel()
{
    int e = blockIdx.x * blockDim.x + threadIdx.x;
    if (e < N_EDGES) atomicAdd(&g_dis[g_dst[e]], 1.0f);
}
__global__ void deg_finalize_kernel()
{
    int i = blockIdx.x * blockDim.x + threadIdx.x;
    if (i < N_NODES) g_dis[i] = rsqrtf(g_dis[i]);
}
__global__ void selfloop_init_kernel(float* __restrict__ out)
{
    int id = blockIdx.x * blockDim.x + threadIdx.x;
    if (id < N_NODES * DIM / 4) {
        int row = id / (DIM / 4);
        float s = g_dis[row]; s = s * s;
        float4 v = reinterpret_cast<const float4*>(g_A)[id];
        v.x *= s; v.y *= s; v.z *= s; v.w *= s;
        reinterpret_cast<float4*>(out)[id] = v;
    }
}
__global__ void scatter_kernel(float* __restrict__ out)
{
    int id = blockIdx.x * blockDim.x + threadIdx.x;
    if (id >= N_EDGES * (DIM / 4)) return;
    int e   = id >> 6;
    int col = (id & 63) << 2;
    int src = g_src[e];
    int dst = g_dst[e];
    float norm = g_dis[src] * g_dis[dst];
    float4 v = *reinterpret_cast<const float4*>(g_A + (size_t)src * DIM + col);
    float* o = out + (size_t)dst * DIM + col;
    atomicAdd(o + 0, v.x * norm);
    atomicAdd(o + 1, v.y * norm);
    atomicAdd(o + 2, v.z * norm);
    atomicAdd(o + 3, v.w * norm);
}
__global__ void combine_kernel(float* __restrict__ out,
                               const float* __restrict__ b,
                               const float* __restrict__ aLp,
                               const float* __restrict__ aHp)
{
    int id = blockIdx.x * blockDim.x + threadIdx.x;
    if (id >= N_NODES * DIM / 4) return;
    float aL = aLp[0], aH = aHp[0];
    int c4 = (id & (DIM / 4 - 1)) << 2;
    float4 hl = reinterpret_cast<const float4*>(out)[id];
    float4 hh = reinterpret_cast<const float4*>(g_B)[id];
    float4 bb = *reinterpret_cast<const float4*>(b + c4);
    float4 r;
    r.x = aL * (hl.x + bb.x) + aH * hh.x;
    r.y = aL * (hl.y + bb.y) + aH * hh.y;
    r.z = aL * (hl.z + bb.z) + aH * hh.z;
    r.w = aL * (hl.w + bb.w) + aH * hh.w;
    reinterpret_cast<float4*>(out)[id] = r;
}

// ---------------------------------------------------------------------------
extern "C" void kernel_launch(void* const* d_in, const int* in_sizes, int n_in,
                              void* d_out, int out_size)
{
    const float* x      = (const float*)d_in[0];
    const void*  ei_raw = d_in[1];
    const float* lap    = (const float*)d_in[2];
    const float* d_inv  = (const float*)d_in[3];
    const float* W_high = (const float*)d_in[4];
    const float* W_conv = (const float*)d_in[5];
    const float* b_conv = (const float*)d_in[6];
    const float* aL     = (const float*)d_in[7];
    const float* aH     = (const float*)d_in[8];
    float*       out    = (float*)d_out;

    float *pA, *pB, *pC;
    cudaGetSymbolAddress((void**)&pA, g_A);
    cudaGetSymbolAddress((void**)&pB, g_B);
    cudaGetSymbolAddress((void**)&pC, g_C);
    __nv_bfloat16 *pDh, *pDl, *pLh, *pLl, *pBh, *pBl;
    cudaGetSymbolAddress((void**)&pDh, g_dinv_hi);
    cudaGetSymbolAddress((void**)&pDl, g_dinv_lo);
    cudaGetSymbolAddress((void**)&pLh, g_lap_hi);
    cudaGetSymbolAddress((void**)&pLl, g_lap_lo);
    cudaGetSymbolAddress((void**)&pBh, g_Bhi);
    cudaGetSymbolAddress((void**)&pBl, g_Blo);

    cudaFuncSetAttribute(gemm_mma_kernel, cudaFuncAttributeMaxDynamicSharedMemorySize, GEMM_SMEM);

    // Edge normalization
    detect_dtype_kernel <<<1, 32>>>((const unsigned int*)ei_raw);
    convert_edges_kernel<<<N_EDGES / 256, 256>>>(ei_raw);

    // Split the two big matrices into bf16 hi/lo
    int nbig4 = N_NODES * N_NODES / 4;
    split_kernel<<<nbig4 / 256, 256>>>((const float4*)d_inv, (uint2*)pDh, (uint2*)pDl, nbig4);
    split_kernel<<<nbig4 / 256, 256>>>((const float4*)lap,   (uint2*)pLh, (uint2*)pLl, nbig4);

    dim3 gS(DIM / 64, N_NODES / 128);
    dim3 gM(DIM / 64, N_NODES / 128);        // (4, 32) = 128 CTAs
    dim3 gTr(N_NODES / 32, DIM / 32);
    dim3 bTr(32, 8);

    // R = relu(x @ W_high); split-transpose
    sgemm_kernel<true><<<gS, 256>>>(x, W_high, pA, N_NODES, DIM, DIM);
    transpose_split_kernel<<<gTr, bTr>>>(pA, pBh, pBl);
    // T1 = d_inv @ R
    gemm_mma_kernel<<<gM, 256, GEMM_SMEM>>>(pDh, pDl, pBh, pBl, pC);
    // XW_conv (reuses g_A)
    sgemm_kernel<false><<<gS, 256>>>(x, W_conv, pA, N_NODES, DIM, DIM);
    // T2 = lap @ T1
    transpose_split_kernel<<<gTr, bTr>>>(pC, pBh, pBl);
    gemm_mma_kernel<<<gM, 256, GEMM_SMEM>>>(pLh, pLl, pBh, pBl, pC);
    // Hh = d_inv @ T2
    transpose_split_kernel<<<gTr, bTr>>>(pC, pBh, pBl);
    gemm_mma_kernel<<<gM, 256, GEMM_SMEM>>>(pDh, pDl, pBh, pBl, pB);

    // GCN branch
    deg_init_kernel    <<<N_NODES / 256, 256>>>();
    deg_count_kernel   <<<N_EDGES / 256, 256>>>();
    deg_finalize_kernel<<<N_NODES / 256, 256>>>();
    int nvec = N_NODES * DIM / 4;
    selfloop_init_kernel<<<(nvec + 255) / 256, 256>>>(out);
    int nscat = N_EDGES * (DIM / 4);
    scatter_kernel<<<(nscat + 255) / 256, 256>>>(out);
    combine_kernel<<<(nvec + 255) / 256, 256>>>(out, b_conv, aL, aH);
}

// round 5
// speedup vs baseline: 3.5013x; 2.0467x over previous
#include <cuda_runtime.h>
#include <cuda_bf16.h>
#include <cstdint>

// FBGCN layer:
//   Hh = d_inv @ (lap @ (d_inv @ relu(x @ W_high)))  -- 3 mma.sync bf16-split GEMMs (split-K=2)
//   Hl = GCNConv(x, edge_index, W_conv, b_conv)
//   out = aL*Hl + aH*Hh

static constexpr int N_NODES = 4096;
static constexpr int DIM     = 256;
static constexpr int N_EDGES = 131072;

// fp32 scratch
__device__ __align__(16) float g_A[N_NODES * DIM];   // R / XW_conv
__device__ __align__(16) float g_B[N_NODES * DIM];   // Hh part0
__device__ __align__(16) float g_C[N_NODES * DIM];   // T part0
__device__ __align__(16) float g_D[N_NODES * DIM];   // split-K part1
__device__ float g_dis[N_NODES];
__device__ int   g_src[N_EDGES];
__device__ int   g_dst[N_EDGES];
__device__ int   g_is64;

// bf16 split buffers
__device__ __align__(128) __nv_bfloat16 g_dinv_hi[N_NODES * N_NODES];
__device__ __align__(128) __nv_bfloat16 g_dinv_lo[N_NODES * N_NODES];
__device__ __align__(128) __nv_bfloat16 g_lap_hi [N_NODES * N_NODES];
__device__ __align__(128) __nv_bfloat16 g_lap_lo [N_NODES * N_NODES];
__device__ __align__(128) __nv_bfloat16 g_Bhi[DIM * N_NODES];   // [256 x 4096] transposed
__device__ __align__(128) __nv_bfloat16 g_Blo[DIM * N_NODES];

// ---------------------------------------------------------------------------
// PTX helpers (baseline ISA only: cp.async, ldmatrix, mma.sync)
// ---------------------------------------------------------------------------
__device__ __forceinline__ uint32_t smem_u32(const void* p) {
    uint32_t a;
    asm("{ .reg .u64 t; cvta.to.shared.u64 t, %1; cvt.u32.u64 %0, t; }" : "=r"(a) : "l"(p));
    return a;
}
__device__ __forceinline__ void cp_async16(uint32_t dst, const void* src) {
    asm volatile("cp.async.cg.shared.global [%0], [%1], 16;" :: "r"(dst), "l"(src) : "memory");
}
__device__ __forceinline__ void cp_commit() { asm volatile("cp.async.commit_group;" ::: "memory"); }
template <int N>
__device__ __forceinline__ void cp_wait() { asm volatile("cp.async.wait_group %0;" :: "n"(N) : "memory"); }

__device__ __forceinline__ void ldsm_x4(uint32_t* r, uint32_t addr) {
    asm volatile("ldmatrix.sync.aligned.m8n8.x4.shared.b16 {%0,%1,%2,%3}, [%4];"
        : "=r"(r[0]), "=r"(r[1]), "=r"(r[2]), "=r"(r[3]) : "r"(addr));
}
__device__ __forceinline__ void mma16816(float* c, const uint32_t* a, const uint32_t* b) {
    asm volatile("mma.sync.aligned.m16n8k16.row.col.f32.bf16.bf16.f32 "
        "{%0,%1,%2,%3}, {%4,%5,%6,%7}, {%8,%9}, {%0,%1,%2,%3};"
        : "+f"(c[0]), "+f"(c[1]), "+f"(c[2]), "+f"(c[3])
        : "r"(a[0]), "r"(a[1]), "r"(a[2]), "r"(a[3]), "r"(b[0]), "r"(b[1]));
}

// ---------------------------------------------------------------------------
// Edge-index dtype detect + normalize
// ---------------------------------------------------------------------------
__global__ void detect_dtype_kernel(const unsigned int* __restrict__ raw)
{
    if (threadIdx.x == 0 && blockIdx.x == 0) {
        int is64 = 1;
        #pragma unroll 1
        for (int i = 0; i < 128; i++)
            if (raw[2 * i + 1] != 0u) { is64 = 0; break; }
        g_is64 = is64;
    }
}
__global__ void convert_edges_kernel(const void* __restrict__ rawp)
{
    int e = blockIdx.x * blockDim.x + threadIdx.x;
    if (e >= N_EDGES) return;
    if (g_is64) {
        const long long* ei = (const long long*)rawp;
        g_src[e] = (int)ei[e];
        g_dst[e] = (int)ei[N_EDGES + e];
    } else {
        const int* ei = (const int*)rawp;
        g_src[e] = ei[e];
        g_dst[e] = ei[N_EDGES + e];
    }
}

// ---------------------------------------------------------------------------
// fp32 -> (hi, lo) bf16 split, same layout
// ---------------------------------------------------------------------------
__global__ void split_kernel(const float4* __restrict__ src,
                             uint2* __restrict__ hi, uint2* __restrict__ lo, int n4)
{
    int id = blockIdx.x * blockDim.x + threadIdx.x;
    if (id >= n4) return;
    float4 v = src[id];
    __nv_bfloat16 hx = __float2bfloat16(v.x), hy = __float2bfloat16(v.y);
    __nv_bfloat16 hz = __float2bfloat16(v.z), hw = __float2bfloat16(v.w);
    __nv_bfloat16 lx = __float2bfloat16(v.x - __bfloat162float(hx));
    __nv_bfloat16 ly = __float2bfloat16(v.y - __bfloat162float(hy));
    __nv_bfloat16 lz = __float2bfloat16(v.z - __bfloat162float(hz));
    __nv_bfloat16 lw = __float2bfloat16(v.w - __bfloat162float(hw));
    __nv_bfloat162 h01(hx, hy), h23(hz, hw), l01(lx, ly), l23(lz, lw);
    uint2 H, L;
    H.x = *(uint32_t*)&h01; H.y = *(uint32_t*)&h23;
    L.x = *(uint32_t*)&l01; L.y = *(uint32_t*)&l23;
    hi[id] = H; lo[id] = L;
}

// ---------------------------------------------------------------------------
// fp32 [4096 x 256] (optionally sum of two buffers) -> transposed bf16 splits
// ---------------------------------------------------------------------------
template <bool SUM2>
__global__ void transpose_split_kernel(const float* __restrict__ src0,
                                       const float* __restrict__ src1,
                                       __nv_bfloat16* __restrict__ hi,
                                       __nv_bfloat16* __restrict__ lo)
{
    __shared__ float tile[32][33];
    int k0 = blockIdx.x * 32;
    int n0 = blockIdx.y * 32;
    int tx = threadIdx.x, ty = threadIdx.y;    // 32 x 8
    #pragma unroll
    for (int j = 0; j < 4; j++) {
        size_t o = (size_t)(k0 + ty + j * 8) * DIM + n0 + tx;
        float v = src0[o];
        if (SUM2) v += src1[o];
        tile[ty + j * 8][tx] = v;
    }
    __syncthreads();
    #pragma unroll
    for (int j = 0; j < 4; j++) {
        int n = ty + j * 8;
        float v = tile[tx][n];
        __nv_bfloat16 h = __float2bfloat16(v);
        __nv_bfloat16 l = __float2bfloat16(v - __bfloat162float(h));
        size_t o = (size_t)(n0 + n) * N_NODES + k0 + tx;
        hi[o] = h; lo[o] = l;
    }
}

// ---------------------------------------------------------------------------
// mma.sync GEMM, split-K=2: Cz[4096x256] f32 = partial sums over 3 segments
//   A segs [4096 x 4096] bf16 K-major rows; B segs [256 x 4096] bf16 K-major rows.
// CTA tile 128(M) x 64(N), BK=32, 256 threads / 8 warps (4x2), warp tile 32x32.
// 4-stage cp.async pipeline, padded 80B rows. blockIdx.z selects K half.
// ---------------------------------------------------------------------------
static constexpr int STAGES   = 4;
static constexpr int BK       = 32;
static constexpr int NIT      = 3 * N_NODES / BK;     // 384 total
static constexpr int NIT_Z    = NIT / 2;              // 192 per z
static constexpr int ROWB     = 80;
static constexpr int A_BYTES  = 128 * ROWB;           // 10240
static constexpr int B_BYTES  = 64 * ROWB;            // 5120
static constexpr int STAGE_B  = A_BYTES + B_BYTES;    // 15360
static constexpr int GEMM_SMEM = STAGES * STAGE_B;    // 61440

__global__ __launch_bounds__(256, 2) void gemm_mma_kernel(
    const __nv_bfloat16* __restrict__ Ahi, const __nv_bfloat16* __restrict__ Alo,
    const __nv_bfloat16* __restrict__ Bhi, const __nv_bfloat16* __restrict__ Blo,
    float* __restrict__ C0, float* __restrict__ C1)
{
    extern __shared__ char smem[];
    const uint32_t sbase = smem_u32(smem);
    const int t    = threadIdx.x;
    const int lane = t & 31;
    const int wid  = t >> 5;
    const int wm   = wid >> 1;
    const int wn   = wid & 1;
    const int m0   = blockIdx.y * 128;
    const int n0   = blockIdx.x * 64;
    const int z    = blockIdx.z;
    const int cBeg = z * NIT_Z;

    const __nv_bfloat16* Aseg[3] = { Ahi, Ahi, Alo };
    const __nv_bfloat16* Bseg[3] = { Bhi, Blo, Bhi };

    const int arow = t >> 2;
    const int ach  = t & 3;
    const size_t aOffG = (size_t)(m0 + arow) * N_NODES + ach * 8;
    const uint32_t aOffS = arow * ROWB + ach * 16;
    const size_t bOffG = (size_t)(n0 + arow) * N_NODES + ach * 8;
    const uint32_t bOffS = arow * ROWB + ach * 16;

    const uint32_t aLd = (uint32_t)(wm * 32 + (lane & 15)) * ROWB + (lane >> 4) * 16;
    const uint32_t bLd = A_BYTES +
        (uint32_t)(wn * 32 + ((lane >> 4) & 1) * 8 + (lane & 7)) * ROWB + ((lane >> 3) & 1) * 16;

    float acc[2][4][4];
    #pragma unroll
    for (int i = 0; i < 2; i++)
        #pragma unroll
        for (int j = 0; j < 4; j++)
            #pragma unroll
            for (int e = 0; e < 4; e++) acc[i][j][e] = 0.f;

    auto load_stage = [&](int ci, int s) {       // ci: local iter index
        if (ci < NIT_Z) {
            int c   = cBeg + ci;
            int seg = c >> 7;
            int k0  = (c & 127) << 5;
            const __nv_bfloat16* ap = Aseg[seg] + aOffG + k0;
            const __nv_bfloat16* bp = Bseg[seg] + bOffG + k0;
            uint32_t sb = sbase + s * STAGE_B;
            cp_async16(sb + aOffS, ap);
            cp_async16(sb + aOffS + 64 * ROWB, ap + (size_t)64 * N_NODES);
            cp_async16(sb + A_BYTES + bOffS, bp);
        }
        cp_commit();
    };

    #pragma unroll
    for (int p = 0; p < STAGES - 1; p++) load_stage(p, p);

    for (int ci = 0; ci < NIT_Z; ci++) {
        cp_wait<STAGES - 2>();
        __syncthreads();
        load_stage(ci + STAGES - 1, (ci + STAGES - 1) % STAGES);

        uint32_t sb = sbase + (ci % STAGES) * STAGE_B;
        // hoist all fragment loads for BK=32, then issue all 16 HMMAs
        uint32_t a[2][2][4], b[2][2][4];
        #pragma unroll
        for (int ks = 0; ks < 2; ks++) {
            ldsm_x4(a[ks][0], sb + aLd + ks * 32);
            ldsm_x4(a[ks][1], sb + aLd + 16 * ROWB + ks * 32);
            ldsm_x4(b[ks][0], sb + bLd + ks * 32);
            ldsm_x4(b[ks][1], sb + bLd + 16 * ROWB + ks * 32);
        }
        #pragma unroll
        for (int ks = 0; ks < 2; ks++) {
            #pragma unroll
            for (int i = 0; i < 2; i++) {
                mma16816(acc[i][0], a[ks][i], &b[ks][0][0]);
                mma16816(acc[i][1], a[ks][i], &b[ks][0][2]);
                mma16816(acc[i][2], a[ks][i], &b[ks][1][0]);
                mma16816(acc[i][3], a[ks][i], &b[ks][1][2]);
            }
        }
    }

    float* C = z ? C1 : C0;
    const int gid = lane >> 2;
    const int tig = lane & 3;
    #pragma unroll
    for (int i = 0; i < 2; i++) {
        int rbase = m0 + wm * 32 + i * 16 + gid;
        #pragma unroll
        for (int j = 0; j < 4; j++) {
            int col = n0 + wn * 32 + j * 8 + tig * 2;
            float2 v0 = { acc[i][j][0], acc[i][j][1] };
            float2 v1 = { acc[i][j][2], acc[i][j][3] };
            *reinterpret_cast<float2*>(C + (size_t)rbase * DIM + col) = v0;
            *reinterpret_cast<float2*>(C + (size_t)(rbase + 8) * DIM + col) = v1;
        }
    }
}

// ---------------------------------------------------------------------------
// SIMT SGEMM for the two small x@W GEMMs (M=4096, N=256, K=256)
// ---------------------------------------------------------------------------
template <bool RELU>
__global__ __launch_bounds__(256, 2) void sgemm_kernel(
    const float* __restrict__ A, const float* __restrict__ B,
    float* __restrict__ C, int M, int N, int K)
{
    __shared__ float As[16][132];
    __shared__ float Bs[16][64];

    const int t  = threadIdx.x;
    const int tx = t & 15;
    const int ty = t >> 4;
    const int m0 = blockIdx.y * 128;
    const int n0 = blockIdx.x * 64;

    const float* Ap = A + (size_t)m0 * K;
    const float* Bp = B + n0;

    float acc[8][4];
    #pragma unroll
    for (int i = 0; i < 8; i++)
        #pragma unroll
        for (int j = 0; j < 4; j++) acc[i][j] = 0.f;

    for (int k0 = 0; k0 < K; k0 += 16) {
        #pragma unroll
        for (int i = 0; i < 2; i++) {
            int f = t + i * 256;
            int row = f >> 2;
            int kc  = (f & 3) << 2;
            float4 v = *reinterpret_cast<const float4*>(Ap + (size_t)row * K + k0 + kc);
            As[kc + 0][row] = v.x; As[kc + 1][row] = v.y;
            As[kc + 2][row] = v.z; As[kc + 3][row] = v.w;
        }
        {
            int kr = t >> 4;
            int c4 = (t & 15) << 2;
            float4 v = *reinterpret_cast<const float4*>(Bp + (size_t)(k0 + kr) * N + c4);
            *reinterpret_cast<float4*>(&Bs[kr][c4]) = v;
        }
        __syncthreads();
        #pragma unroll
        for (int k = 0; k < 16; k++) {
            float a[8], b[4];
            float4 a0 = *reinterpret_cast<const float4*>(&As[k][ty * 8]);
            float4 a1 = *reinterpret_cast<const float4*>(&As[k][ty * 8 + 4]);
            a[0]=a0.x; a[1]=a0.y; a[2]=a0.z; a[3]=a0.w;
            a[4]=a1.x; a[5]=a1.y; a[6]=a1.z; a[7]=a1.w;
            float4 b0 = *reinterpret_cast<const float4*>(&Bs[k][tx * 4]);
            b[0]=b0.x; b[1]=b0.y; b[2]=b0.z; b[3]=b0.w;
            #pragma unroll
            for (int i = 0; i < 8; i++)
                #pragma unroll
                for (int j = 0; j < 4; j++)
                    acc[i][j] = fmaf(a[i], b[j], acc[i][j]);
        }
        __syncthreads();
    }
    #pragma unroll
    for (int i = 0; i < 8; i++) {
        int r = m0 + ty * 8 + i;
        float4 v;
        v.x = acc[i][0]; v.y = acc[i][1]; v.z = acc[i][2]; v.w = acc[i][3];
        if (RELU) {
            v.x = fmaxf(v.x, 0.f); v.y = fmaxf(v.y, 0.f);
            v.z = fmaxf(v.z, 0.f); v.w = fmaxf(v.w, 0.f);
        }
        *reinterpret_cast<float4*>(C + (size_t)r * N + n0 + tx * 4) = v;
    }
}

// ---------------------------------------------------------------------------
// GCN branch
// ---------------------------------------------------------------------------
__global__ void deg_init_kernel()
{
    int i = blockIdx.x * blockDim.x + threadIdx.x;
    if (i < N_NODES) g_dis[i] = 1.0f;
}
__global__ void deg_count_kernel()
{
    int e = blockIdx.x * blockDim.x + threadIdx.x;
    if (e < N_EDGES) atomicAdd(&g_dis[g_dst[e]], 1.0f);
}
__global__ void deg_finalize_kernel()
{
    int i = blockIdx.x * blockDim.x + threadIdx.x;
    if (i < N_NODES) g_dis[i] = rsqrtf(g_dis[i]);
}
__global__ void selfloop_init_kernel(float* __restrict__ out)
{
    int id = blockIdx.x * blockDim.x + threadIdx.x;
    if (id < N_NODES * DIM / 4) {
        int row = id / (DIM / 4);
        float s = g_dis[row]; s = s * s;
        float4 v = reinterpret_cast<const float4*>(g_A)[id];
        v.x *= s; v.y *= s; v.z *= s; v.w *= s;
        reinterpret_cast<float4*>(out)[id] = v;
    }
}
__global__ void scatter_kernel(float* __restrict__ out)
{
    int id = blockIdx.x * blockDim.x + threadIdx.x;
    if (id >= N_EDGES * (DIM / 4)) return;
    int e   = id >> 6;
    int col = (id & 63) << 2;
    int src = g_src[e];
    int dst = g_dst[e];
    float norm = g_dis[src] * g_dis[dst];
    float4 v = *reinterpret_cast<const float4*>(g_A + (size_t)src * DIM + col);
    float* o = out + (size_t)dst * DIM + col;
    atomicAdd(o + 0, v.x * norm);
    atomicAdd(o + 1, v.y * norm);
    atomicAdd(o + 2, v.z * norm);
    atomicAdd(o + 3, v.w * norm);
}
__global__ void combine_kernel(float* __restrict__ out,
                               const float* __restrict__ b,
                               const float* __restrict__ aLp,
                               const float* __restrict__ aHp)
{
    int id = blockIdx.x * blockDim.x + threadIdx.x;
    if (id >= N_NODES * DIM / 4) return;
    float aL = aLp[0], aH = aHp[0];
    int c4 = (id & (DIM / 4 - 1)) << 2;
    float4 hl = reinterpret_cast<const float4*>(out)[id];
    float4 h0 = reinterpret_cast<const float4*>(g_B)[id];
    float4 h1 = reinterpret_cast<const float4*>(g_D)[id];
    float4 bb = *reinterpret_cast<const float4*>(b + c4);
    float4 r;
    r.x = aL * (hl.x + bb.x) + aH * (h0.x + h1.x);
    r.y = aL * (hl.y + bb.y) + aH * (h0.y + h1.y);
    r.z = aL * (hl.z + bb.z) + aH * (h0.z + h1.z);
    r.w = aL * (hl.w + bb.w) + aH * (h0.w + h1.w);
    reinterpret_cast<float4*>(out)[id] = r;
}

// ---------------------------------------------------------------------------
extern "C" void kernel_launch(void* const* d_in, const int* in_sizes, int n_in,
                              void* d_out, int out_size)
{
    const float* x      = (const float*)d_in[0];
    const void*  ei_raw = d_in[1];
    const float* lap    = (const float*)d_in[2];
    const float* d_inv  = (const float*)d_in[3];
    const float* W_high = (const float*)d_in[4];
    const float* W_conv = (const float*)d_in[5];
    const float* b_conv = (const float*)d_in[6];
    const float* aL     = (const float*)d_in[7];
    const float* aH     = (const float*)d_in[8];
    float*       out    = (float*)d_out;

    float *pA, *pB, *pC, *pD;
    cudaGetSymbolAddress((void**)&pA, g_A);
    cudaGetSymbolAddress((void**)&pB, g_B);
    cudaGetSymbolAddress((void**)&pC, g_C);
    cudaGetSymbolAddress((void**)&pD, g_D);
    __nv_bfloat16 *pDh, *pDl, *pLh, *pLl, *pBh, *pBl;
    cudaGetSymbolAddress((void**)&pDh, g_dinv_hi);
    cudaGetSymbolAddress((void**)&pDl, g_dinv_lo);
    cudaGetSymbolAddress((void**)&pLh, g_lap_hi);
    cudaGetSymbolAddress((void**)&pLl, g_lap_lo);
    cudaGetSymbolAddress((void**)&pBh, g_Bhi);
    cudaGetSymbolAddress((void**)&pBl, g_Blo);

    cudaFuncSetAttribute(gemm_mma_kernel, cudaFuncAttributeMaxDynamicSharedMemorySize, GEMM_SMEM);

    // Edge normalization
    detect_dtype_kernel <<<1, 32>>>((const unsigned int*)ei_raw);
    convert_edges_kernel<<<N_EDGES / 256, 256>>>(ei_raw);

    // Split the two big matrices into bf16 hi/lo
    int nbig4 = N_NODES * N_NODES / 4;
    split_kernel<<<nbig4 / 256, 256>>>((const float4*)d_inv, (uint2*)pDh, (uint2*)pDl, nbig4);
    split_kernel<<<nbig4 / 256, 256>>>((const float4*)lap,   (uint2*)pLh, (uint2*)pLl, nbig4);

    dim3 gS(DIM / 64, N_NODES / 128);
    dim3 gM(DIM / 64, N_NODES / 128, 2);     // (4, 32, 2) = 256 CTAs
    dim3 gTr(N_NODES / 32, DIM / 32);
    dim3 bTr(32, 8);

    // R = relu(x @ W_high); split-transpose
    sgemm_kernel<true><<<gS, 256>>>(x, W_high, pA, N_NODES, DIM, DIM);
    transpose_split_kernel<false><<<gTr, bTr>>>(pA, nullptr, pBh, pBl);
    // T1 = d_inv @ R (parts in g_C, g_D)
    gemm_mma_kernel<<<gM, 256, GEMM_SMEM>>>(pDh, pDl, pBh, pBl, pC, pD);
    // XW_conv (reuses g_A)
    sgemm_kernel<false><<<gS, 256>>>(x, W_conv, pA, N_NODES, DIM, DIM);
    // T2 = lap @ T1
    transpose_split_kernel<true><<<gTr, bTr>>>(pC, pD, pBh, pBl);
    gemm_mma_kernel<<<gM, 256, GEMM_SMEM>>>(pLh, pLl, pBh, pBl, pC, pD);
    // Hh = d_inv @ T2 (parts in g_B, g_D)
    transpose_split_kernel<true><<<gTr, bTr>>>(pC, pD, pBh, pBl);
    gemm_mma_kernel<<<gM, 256, GEMM_SMEM>>>(pDh, pDl, pBh, pBl, pB, pD);

    // GCN branch
    deg_init_kernel    <<<N_NODES / 256, 256>>>();
    deg_count_kernel   <<<N_EDGES / 256, 256>>>();
    deg_finalize_kernel<<<N_NODES / 256, 256>>>();
    int nvec = N_NODES * DIM / 4;
    selfloop_init_kernel<<<(nvec + 255) / 256, 256>>>(out);
    int nscat = N_EDGES * (DIM / 4);
    scatter_kernel<<<(nscat + 255) / 256, 256>>>(out);
    combine_kernel<<<(nvec + 255) / 256, 256>>>(out, b_conv, aL, aH);
}

// round 6
// speedup vs baseline: 3.9783x; 1.1363x over previous
#include <cuda_runtime.h>
#include <cuda_bf16.h>
#include <cstdint>

// FBGCN layer:
//   Hh = d_inv @ (lap @ (d_inv @ relu(x @ W_high)))  -- mma.sync bf16-split GEMMs
//   Hl = GCNConv(x, edge_index, W_conv, b_conv)
//   out = aL*Hl + aH*Hh

static constexpr int N_NODES = 4096;
static constexpr int DIM     = 256;
static constexpr int N_EDGES = 131072;

// fp32 scratch
__device__ __align__(16) float g_A[N_NODES * DIM];    // R / XW_conv
__device__ __align__(16) float g_P0[N_NODES * DIM];   // split-K partials
__device__ __align__(16) float g_P1[N_NODES * DIM];
__device__ __align__(16) float g_P2[N_NODES * DIM];
__device__ __align__(16) float g_P3[N_NODES * DIM];
__device__ float g_dis[N_NODES];
__device__ int   g_src[N_EDGES];
__device__ int   g_dst[N_EDGES];
__device__ int   g_is64;

// bf16 split buffers
__device__ __align__(128) __nv_bfloat16 g_dinv_hi[N_NODES * N_NODES];
__device__ __align__(128) __nv_bfloat16 g_dinv_lo[N_NODES * N_NODES];
__device__ __align__(128) __nv_bfloat16 g_lap_hi [N_NODES * N_NODES];
__device__ __align__(128) __nv_bfloat16 g_lap_lo [N_NODES * N_NODES];
__device__ __align__(128) __nv_bfloat16 g_Bhi[DIM * N_NODES];   // [256 x 4096] act^T
__device__ __align__(128) __nv_bfloat16 g_Blo[DIM * N_NODES];
__device__ __align__(128) __nv_bfloat16 g_xhi[N_NODES * DIM];   // x splits (K-major rows)
__device__ __align__(128) __nv_bfloat16 g_xlo[N_NODES * DIM];
__device__ __align__(128) __nv_bfloat16 g_Wth[DIM * DIM];       // W^T splits
__device__ __align__(128) __nv_bfloat16 g_Wtl[DIM * DIM];

// ---------------------------------------------------------------------------
// PTX helpers (baseline ISA only: cp.async, ldmatrix, mma.sync)
// ---------------------------------------------------------------------------
__device__ __forceinline__ uint32_t smem_u32(const void* p) {
    uint32_t a;
    asm("{ .reg .u64 t; cvta.to.shared.u64 t, %1; cvt.u32.u64 %0, t; }" : "=r"(a) : "l"(p));
    return a;
}
__device__ __forceinline__ void cp_async16(uint32_t dst, const void* src) {
    asm volatile("cp.async.cg.shared.global [%0], [%1], 16;" :: "r"(dst), "l"(src) : "memory");
}
__device__ __forceinline__ void cp_commit() { asm volatile("cp.async.commit_group;" ::: "memory"); }
template <int N>
__device__ __forceinline__ void cp_wait() { asm volatile("cp.async.wait_group %0;" :: "n"(N) : "memory"); }

__device__ __forceinline__ void ldsm_x4(uint32_t* r, uint32_t addr) {
    asm volatile("ldmatrix.sync.aligned.m8n8.x4.shared.b16 {%0,%1,%2,%3}, [%4];"
        : "=r"(r[0]), "=r"(r[1]), "=r"(r[2]), "=r"(r[3]) : "r"(addr));
}
__device__ __forceinline__ void mma16816(float* c, const uint32_t* a, const uint32_t* b) {
    asm volatile("mma.sync.aligned.m16n8k16.row.col.f32.bf16.bf16.f32 "
        "{%0,%1,%2,%3}, {%4,%5,%6,%7}, {%8,%9}, {%0,%1,%2,%3};"
        : "+f"(c[0]), "+f"(c[1]), "+f"(c[2]), "+f"(c[3])
        : "r"(a[0]), "r"(a[1]), "r"(a[2]), "r"(a[3]), "r"(b[0]), "r"(b[1]));
}

// ---------------------------------------------------------------------------
// Edge-index dtype detect + normalize
// ---------------------------------------------------------------------------
__global__ void detect_dtype_kernel(const unsigned int* __restrict__ raw)
{
    if (threadIdx.x == 0 && blockIdx.x == 0) {
        int is64 = 1;
        #pragma unroll 1
        for (int i = 0; i < 128; i++)
            if (raw[2 * i + 1] != 0u) { is64 = 0; break; }
        g_is64 = is64;
    }
}
__global__ void convert_edges_kernel(const void* __restrict__ rawp)
{
    int e = blockIdx.x * blockDim.x + threadIdx.x;
    if (e >= N_EDGES) return;
    if (g_is64) {
        const long long* ei = (const long long*)rawp;
        g_src[e] = (int)ei[e];
        g_dst[e] = (int)ei[N_EDGES + e];
    } else {
        const int* ei = (const int*)rawp;
        g_src[e] = ei[e];
        g_dst[e] = ei[N_EDGES + e];
    }
}

// ---------------------------------------------------------------------------
// fp32 -> (hi, lo) bf16 split, same layout
// ---------------------------------------------------------------------------
__global__ void split_kernel(const float4* __restrict__ src,
                             uint2* __restrict__ hi, uint2* __restrict__ lo, int n4)
{
    int id = blockIdx.x * blockDim.x + threadIdx.x;
    if (id >= n4) return;
    float4 v = src[id];
    __nv_bfloat16 hx = __float2bfloat16(v.x), hy = __float2bfloat16(v.y);
    __nv_bfloat16 hz = __float2bfloat16(v.z), hw = __float2bfloat16(v.w);
    __nv_bfloat16 lx = __float2bfloat16(v.x - __bfloat162float(hx));
    __nv_bfloat16 ly = __float2bfloat16(v.y - __bfloat162float(hy));
    __nv_bfloat16 lz = __float2bfloat16(v.z - __bfloat162float(hz));
    __nv_bfloat16 lw = __float2bfloat16(v.w - __bfloat162float(hw));
    __nv_bfloat162 h01(hx, hy), h23(hz, hw), l01(lx, ly), l23(lz, lw);
    uint2 H, L;
    H.x = *(uint32_t*)&h01; H.y = *(uint32_t*)&h23;
    L.x = *(uint32_t*)&l01; L.y = *(uint32_t*)&l23;
    hi[id] = H; lo[id] = L;
}

// ---------------------------------------------------------------------------
// activations: fp32 [4096 x 256] (sum of NSUM buffers) -> bf16 splits [256 x 4096]
// ---------------------------------------------------------------------------
template <int NSUM>
__global__ void transpose_split_kernel(const float* __restrict__ s0,
                                       const float* __restrict__ s1,
                                       const float* __restrict__ s2,
                                       const float* __restrict__ s3,
                                       __nv_bfloat16* __restrict__ hi,
                                       __nv_bfloat16* __restrict__ lo)
{
    __shared__ float tile[32][33];
    int k0 = blockIdx.x * 32;
    int n0 = blockIdx.y * 32;
    int tx = threadIdx.x, ty = threadIdx.y;    // 32 x 8
    #pragma unroll
    for (int j = 0; j < 4; j++) {
        size_t o = (size_t)(k0 + ty + j * 8) * DIM + n0 + tx;
        float v = s0[o];
        if (NSUM > 1) v += s1[o];
        if (NSUM > 2) v += s2[o];
        if (NSUM > 3) v += s3[o];
        tile[ty + j * 8][tx] = v;
    }
    __syncthreads();
    #pragma unroll
    for (int j = 0; j < 4; j++) {
        int n = ty + j * 8;
        float v = tile[tx][n];
        __nv_bfloat16 h = __float2bfloat16(v);
        __nv_bfloat16 l = __float2bfloat16(v - __bfloat162float(h));
        size_t o = (size_t)(n0 + n) * N_NODES + k0 + tx;
        hi[o] = h; lo[o] = l;
    }
}

// W [256 x 256] fp32 row-major -> W^T bf16 splits [256 x 256]
__global__ void wtranspose_split_kernel(const float* __restrict__ W,
                                        __nv_bfloat16* __restrict__ hi,
                                        __nv_bfloat16* __restrict__ lo)
{
    __shared__ float tile[32][33];
    int k0 = blockIdx.x * 32;
    int n0 = blockIdx.y * 32;
    int tx = threadIdx.x, ty = threadIdx.y;    // 32 x 8
    #pragma unroll
    for (int j = 0; j < 4; j++)
        tile[ty + j * 8][tx] = W[(size_t)(k0 + ty + j * 8) * DIM + n0 + tx];
    __syncthreads();
    #pragma unroll
    for (int j = 0; j < 4; j++) {
        int n = ty + j * 8;
        float v = tile[tx][n];
        __nv_bfloat16 h = __float2bfloat16(v);
        __nv_bfloat16 l = __float2bfloat16(v - __bfloat162float(h));
        size_t o = (size_t)(n0 + n) * DIM + k0 + tx;
        hi[o] = h; lo[o] = l;
    }
}

// ---------------------------------------------------------------------------
// mma.sync GEMM: C[4096 x 256] f32, 3-term bf16 split, optional split-K.
// CTA tile 128(M) x 128(N), BK=64, 256 threads / 8 warps (2m x 4n), warp 64x32.
// ROWB=144: cp.async writes and ldmatrix reads both bank-conflict-free.
// 3-stage cp.async pipeline. blockIdx.z selects K chunk -> partial buffer.
// ---------------------------------------------------------------------------
static constexpr int STAGES   = 3;
static constexpr int ROWB     = 144;                  // 128B data + 16B pad
static constexpr int A_BYTES  = 128 * ROWB;           // 18432
static constexpr int STAGE_B  = 2 * A_BYTES;          // 36864
static constexpr int GEMM_SMEM = STAGES * STAGE_B;    // 110592

template <bool RELU>
__global__ __launch_bounds__(256, 2) void gemm_mma_kernel(
    const __nv_bfloat16* __restrict__ Ahi, const __nv_bfloat16* __restrict__ Alo,
    const __nv_bfloat16* __restrict__ Bhi, const __nv_bfloat16* __restrict__ Blo,
    float* __restrict__ C0, float* __restrict__ C1,
    float* __restrict__ C2, float* __restrict__ C3,
    int strideA, int strideB, int nit, int segShift)
{
    extern __shared__ char smem[];
    const uint32_t sbase = smem_u32(smem);
    const int t    = threadIdx.x;
    const int lane = t & 31;
    const int wid  = t >> 5;
    const int wm   = wid >> 2;       // 0..1 -> M offset wm*64
    const int wn   = wid & 3;        // 0..3 -> N offset wn*32
    const int m0   = blockIdx.y * 128;
    const int n0   = blockIdx.x * 128;
    const int cBeg = blockIdx.z * nit;
    const int segMask = (1 << segShift) - 1;

    const __nv_bfloat16* Aseg[3] = { Ahi, Ahi, Alo };
    const __nv_bfloat16* Bseg[3] = { Bhi, Blo, Bhi };

    // cp.async task mapping: 8 tasks/thread (4 A rows + 4 B rows), ch = t&7
    const int rowBase = t >> 3;          // 0..31
    const int ch      = t & 7;
    uint32_t aOffG[4], bOffG[4], sOffA[4];
    #pragma unroll
    for (int i = 0; i < 4; i++) {
        int row = rowBase + 32 * i;
        aOffG[i] = (uint32_t)((m0 + row) * strideA + ch * 8);
        bOffG[i] = (uint32_t)((n0 + row) * strideB + ch * 8);
        sOffA[i] = (uint32_t)(row * ROWB + ch * 16);
    }

    // ldmatrix lane bases (byte offsets within stage)
    const uint32_t aLd = (uint32_t)(wm * 64 + (lane & 15)) * ROWB + (lane >> 4) * 16;
    const uint32_t bLd = A_BYTES +
        (uint32_t)(wn * 32 + ((lane >> 4) & 1) * 8 + (lane & 7)) * ROWB + ((lane >> 3) & 1) * 16;

    float acc[4][4][4];
    #pragma unroll
    for (int f = 0; f < 4; f++)
        #pragma unroll
        for (int j = 0; j < 4; j++)
            #pragma unroll
            for (int e = 0; e < 4; e++) acc[f][j][e] = 0.f;

    auto load_stage = [&](int ci, int s) {
        if (ci < nit) {
            int c   = cBeg + ci;
            int seg = c >> segShift;
            int k0  = (c & segMask) << 6;
            const __nv_bfloat16* ap = Aseg[seg] + k0;
            const __nv_bfloat16* bp = Bseg[seg] + k0;
            uint32_t sb = sbase + s * STAGE_B;
            #pragma unroll
            for (int i = 0; i < 4; i++) cp_async16(sb + sOffA[i], ap + aOffG[i]);
            #pragma unroll
            for (int i = 0; i < 4; i++) cp_async16(sb + A_BYTES + sOffA[i], bp + bOffG[i]);
        }
        cp_commit();
    };

    load_stage(0, 0);
    load_stage(1, 1);

    for (int ci = 0; ci < nit; ci++) {
        cp_wait<STAGES - 2>();
        __syncthreads();
        load_stage(ci + STAGES - 1, (ci + STAGES - 1) % STAGES);

        uint32_t sb = sbase + (ci % STAGES) * STAGE_B;
        #pragma unroll
        for (int ks = 0; ks < 4; ks++) {
            uint32_t a[4][4], b[2][4];
            #pragma unroll
            for (int f = 0; f < 4; f++)
                ldsm_x4(a[f], sb + aLd + f * 16 * ROWB + ks * 32);
            ldsm_x4(b[0], sb + bLd + ks * 32);
            ldsm_x4(b[1], sb + bLd + 16 * ROWB + ks * 32);
            #pragma unroll
            for (int f = 0; f < 4; f++) {
                mma16816(acc[f][0], a[f], &b[0][0]);
                mma16816(acc[f][1], a[f], &b[0][2]);
                mma16816(acc[f][2], a[f], &b[1][0]);
                mma16816(acc[f][3], a[f], &b[1][2]);
            }
        }
    }

    float* C = (blockIdx.z == 0) ? C0 : (blockIdx.z == 1) ? C1
             : (blockIdx.z == 2) ? C2 : C3;
    const int gid = lane >> 2;
    const int tig = lane & 3;
    #pragma unroll
    for (int f = 0; f < 4; f++) {
        int rbase = m0 + wm * 64 + f * 16 + gid;
        #pragma unroll
        for (int j = 0; j < 4; j++) {
            int col = n0 + wn * 32 + j * 8 + tig * 2;
            float2 v0 = { acc[f][j][0], acc[f][j][1] };
            float2 v1 = { acc[f][j][2], acc[f][j][3] };
            if (RELU) {
                v0.x = fmaxf(v0.x, 0.f); v0.y = fmaxf(v0.y, 0.f);
                v1.x = fmaxf(v1.x, 0.f); v1.y = fmaxf(v1.y, 0.f);
            }
            *reinterpret_cast<float2*>(C + (size_t)rbase * DIM + col) = v0;
            *reinterpret_cast<float2*>(C + (size_t)(rbase + 8) * DIM + col) = v1;
        }
    }
}

// ---------------------------------------------------------------------------
// GCN branch
// ---------------------------------------------------------------------------
__global__ void deg_init_kernel()
{
    int i = blockIdx.x * blockDim.x + threadIdx.x;
    if (i < N_NODES) g_dis[i] = 1.0f;
}
__global__ void deg_count_kernel()
{
    int e = blockIdx.x * blockDim.x + threadIdx.x;
    if (e < N_EDGES) atomicAdd(&g_dis[g_dst[e]], 1.0f);
}
__global__ void deg_finalize_kernel()
{
    int i = blockIdx.x * blockDim.x + threadIdx.x;
    if (i < N_NODES) g_dis[i] = rsqrtf(g_dis[i]);
}
__global__ void selfloop_init_kernel(float* __restrict__ out)
{
    int id = blockIdx.x * blockDim.x + threadIdx.x;
    if (id < N_NODES * DIM / 4) {
        int row = id / (DIM / 4);
        float s = g_dis[row]; s = s * s;
        float4 v = reinterpret_cast<const float4*>(g_A)[id];
        v.x *= s; v.y *= s; v.z *= s; v.w *= s;
        reinterpret_cast<float4*>(out)[id] = v;
    }
}
__global__ void scatter_kernel(float* __restrict__ out)
{
    int id = blockIdx.x * blockDim.x + threadIdx.x;
    if (id >= N_EDGES * (DIM / 4)) return;
    int e   = id >> 6;
    int col = (id & 63) << 2;
    int src = g_src[e];
    int dst = g_dst[e];
    float norm = g_dis[src] * g_dis[dst];
    float4 v = *reinterpret_cast<const float4*>(g_A + (size_t)src * DIM + col);
    float* o = out + (size_t)dst * DIM + col;
    atomicAdd(o + 0, v.x * norm);
    atomicAdd(o + 1, v.y * norm);
    atomicAdd(o + 2, v.z * norm);
    atomicAdd(o + 3, v.w * norm);
}
__global__ void combine_kernel(float* __restrict__ out,
                               const float* __restrict__ b,
                               const float* __restrict__ aLp,
                               const float* __restrict__ aHp)
{
    int id = blockIdx.x * blockDim.x + threadIdx.x;
    if (id >= N_NODES * DIM / 4) return;
    float aL = aLp[0], aH = aHp[0];
    int c4 = (id & (DIM / 4 - 1)) << 2;
    float4 hl = reinterpret_cast<const float4*>(out)[id];
    float4 h0 = reinterpret_cast<const float4*>(g_P0)[id];
    float4 h1 = reinterpret_cast<const float4*>(g_P1)[id];
    float4 h2 = reinterpret_cast<const float4*>(g_P2)[id];
    float4 h3 = reinterpret_cast<const float4*>(g_P3)[id];
    float4 bb = *reinterpret_cast<const float4*>(b + c4);
    float4 r;
    r.x = aL * (hl.x + bb.x) + aH * ((h0.x + h1.x) + (h2.x + h3.x));
    r.y = aL * (hl.y + bb.y) + aH * ((h0.y + h1.y) + (h2.y + h3.y));
    r.z = aL * (hl.z + bb.z) + aH * ((h0.z + h1.z) + (h2.z + h3.z));
    r.w = aL * (hl.w + bb.w) + aH * ((h0.w + h1.w) + (h2.w + h3.w));
    reinterpret_cast<float4*>(out)[id] = r;
}

// ---------------------------------------------------------------------------
extern "C" void kernel_launch(void* const* d_in, const int* in_sizes, int n_in,
                              void* d_out, int out_size)
{
    const float* x      = (const float*)d_in[0];
    const void*  ei_raw = d_in[1];
    const float* lap    = (const float*)d_in[2];
    const float* d_inv  = (const float*)d_in[3];
    const float* W_high = (const float*)d_in[4];
    const float* W_conv = (const float*)d_in[5];
    const float* b_conv = (const float*)d_in[6];
    const float* aL     = (const float*)d_in[7];
    const float* aH     = (const float*)d_in[8];
    float*       out    = (float*)d_out;

    float *pA, *pP0, *pP1, *pP2, *pP3;
    cudaGetSymbolAddress((void**)&pA,  g_A);
    cudaGetSymbolAddress((void**)&pP0, g_P0);
    cudaGetSymbolAddress((void**)&pP1, g_P1);
    cudaGetSymbolAddress((void**)&pP2, g_P2);
    cudaGetSymbolAddress((void**)&pP3, g_P3);
    __nv_bfloat16 *pDh, *pDl, *pLh, *pLl, *pBh, *pBl, *pXh, *pXl, *pWh, *pWl;
    cudaGetSymbolAddress((void**)&pDh, g_dinv_hi);
    cudaGetSymbolAddress((void**)&pDl, g_dinv_lo);
    cudaGetSymbolAddress((void**)&pLh, g_lap_hi);
    cudaGetSymbolAddress((void**)&pLl, g_lap_lo);
    cudaGetSymbolAddress((void**)&pBh, g_Bhi);
    cudaGetSymbolAddress((void**)&pBl, g_Blo);
    cudaGetSymbolAddress((void**)&pXh, g_xhi);
    cudaGetSymbolAddress((void**)&pXl, g_xlo);
    cudaGetSymbolAddress((void**)&pWh, g_Wth);
    cudaGetSymbolAddress((void**)&pWl, g_Wtl);

    cudaFuncSetAttribute(gemm_mma_kernel<false>, cudaFuncAttributeMaxDynamicSharedMemorySize, GEMM_SMEM);
    cudaFuncSetAttribute(gemm_mma_kernel<true >, cudaFuncAttributeMaxDynamicSharedMemorySize, GEMM_SMEM);

    // Edge normalization
    detect_dtype_kernel <<<1, 32>>>((const unsigned int*)ei_raw);
    convert_edges_kernel<<<N_EDGES / 256, 256>>>(ei_raw);

    // Splits of inputs
    int nbig4 = N_NODES * N_NODES / 4;
    split_kernel<<<nbig4 / 256, 256>>>((const float4*)d_inv, (uint2*)pDh, (uint2*)pDl, nbig4);
    split_kernel<<<nbig4 / 256, 256>>>((const float4*)lap,   (uint2*)pLh, (uint2*)pLl, nbig4);
    int nx4 = N_NODES * DIM / 4;
    split_kernel<<<nx4 / 256, 256>>>((const float4*)x, (uint2*)pXh, (uint2*)pXl, nx4);

    dim3 gBig(DIM / 128, N_NODES / 128, 4);  // (2, 32, 4) = 256 CTAs
    dim3 gSm (DIM / 128, N_NODES / 128, 1);  // (2, 32, 1)
    dim3 gTr(N_NODES / 32, DIM / 32);
    dim3 bTr(32, 8);
    dim3 gWt(DIM / 32, DIM / 32);
    const int NIT_BIG = (3 * N_NODES / 64) / 4;   // 48 per z
    const int NIT_SM  = 3 * DIM / 64;             // 12
    const int SEG_BIG = 6;                        // 64 iters / segment
    const int SEG_SM  = 2;                        // 4 iters / segment

    // R = relu(x @ W_high)
    wtranspose_split_kernel<<<gWt, bTr>>>(W_high, pWh, pWl);
    gemm_mma_kernel<true><<<gSm, 256, GEMM_SMEM>>>(pXh, pXl, pWh, pWl,
        pA, pA, pA, pA, DIM, DIM, NIT_SM, SEG_SM);
    transpose_split_kernel<1><<<gTr, bTr>>>(pA, nullptr, nullptr, nullptr, pBh, pBl);
    // T1 = d_inv @ R
    gemm_mma_kernel<false><<<gBig, 256, GEMM_SMEM>>>(pDh, pDl, pBh, pBl,
        pP0, pP1, pP2, pP3, N_NODES, N_NODES, NIT_BIG, SEG_BIG);
    // XW_conv = x @ W_conv (into g_A)
    wtranspose_split_kernel<<<gWt, bTr>>>(W_conv, pWh, pWl);
    gemm_mma_kernel<false><<<gSm, 256, GEMM_SMEM>>>(pXh, pXl, pWh, pWl,
        pA, pA, pA, pA, DIM, DIM, NIT_SM, SEG_SM);
    // T2 = lap @ T1
    transpose_split_kernel<4><<<gTr, bTr>>>(pP0, pP1, pP2, pP3, pBh, pBl);
    gemm_mma_kernel<false><<<gBig, 256, GEMM_SMEM>>>(pLh, pLl, pBh, pBl,
        pP0, pP1, pP2, pP3, N_NODES, N_NODES, NIT_BIG, SEG_BIG);
    // Hh = d_inv @ T2 (parts stay in P0..P3)
    transpose_split_kernel<4><<<gTr, bTr>>>(pP0, pP1, pP2, pP3, pBh, pBl);
    gemm_mma_kernel<false><<<gBig, 256, GEMM_SMEM>>>(pDh, pDl, pBh, pBl,
        pP0, pP1, pP2, pP3, N_NODES, N_NODES, NIT_BIG, SEG_BIG);

    // GCN branch
    deg_init_kernel    <<<N_NODES / 256, 256>>>();
    deg_count_kernel   <<<N_EDGES / 256, 256>>>();
    deg_finalize_kernel<<<N_NODES / 256, 256>>>();
    int nvec = N_NODES * DIM / 4;
    selfloop_init_kernel<<<(nvec + 255) / 256, 256>>>(out);
    int nscat = N_EDGES * (DIM / 4);
    scatter_kernel<<<(nscat + 255) / 256, 256>>>(out);
    combine_kernel<<<(nvec + 255) / 256, 256>>>(out, b_conv, aL, aH);
}